// round 1
// baseline (speedup 1.0000x reference)
#include <cuda_runtime.h>
#include <math.h>

#define HD 512
#define WD 512
#define BD 32
#define NRING 257      // rings 0..256
#define NBINS 258      // +1 drop bin (r > 256)

// Scratch: row-FFT intermediate Fz[b][h][w] (complex). 64 MB static device array.
__device__ float2 g_fft[(size_t)BD * HD * WD];
// Ring accumulators: [r][b][{Cr,Ci,C1,C2}]
__device__ float g_bins[NBINS * BD * 4];

__device__ __forceinline__ float2 cadd(float2 a, float2 b){ return make_float2(a.x+b.x, a.y+b.y); }
__device__ __forceinline__ float2 csub(float2 a, float2 b){ return make_float2(a.x-b.x, a.y-b.y); }
__device__ __forceinline__ float2 cmul(float2 a, float2 b){ return make_float2(a.x*b.x - a.y*b.y, a.x*b.y + a.y*b.x); }

// 512-point forward complex FFT, Stockham autosort, radix-2, 9 stages.
// 128 threads cooperate; x,y are shared ping-pong buffers of 512 float2.
// Returns pointer to buffer holding the (natural-order) result.
__device__ float2* fft512(float2* x, float2* y, int tid) {
    const int m = 256;
    #pragma unroll
    for (int l = 1; l < 512; l <<= 1) {
        __syncthreads();
        #pragma unroll
        for (int q = 0; q < 2; q++) {
            int j = tid + q * 128;           // butterfly index 0..255
            int k = j & (l - 1);
            float s, c;
            sincospif(-(float)k / (float)l, &s, &c);   // w = e^{-i*pi*k/l}
            float2 w = make_float2(c, s);
            float2 a = x[j];
            float2 b = cmul(w, x[j + m]);
            int idx = ((j - k) << 1) + k;
            y[idx]     = cadd(a, b);
            y[idx + l] = csub(a, b);
        }
        float2* t = x; x = y; y = t;
    }
    __syncthreads();
    return x;
}

// ---------------- Pass 1: row FFTs. One block per (b,h) row. ----------------
__global__ void __launch_bounds__(128) pass1_rows(const float* __restrict__ o,
                                                  const float* __restrict__ t) {
    __shared__ float2 bufA[512];
    __shared__ float2 bufB[512];
    int row = blockIdx.x;                    // 0 .. BD*HD-1
    int tid = threadIdx.x;
    const float* op = o + (size_t)row * WD;
    const float* tp = t + (size_t)row * WD;
    #pragma unroll
    for (int w = tid; w < 512; w += 128)
        bufA[w] = make_float2(op[w], tp[w]);          // z = o + i*t
    float2* res = fft512(bufA, bufB, tid);
    float2* out = g_fft + (size_t)row * WD;
    #pragma unroll
    for (int w = tid; w < 512; w += 128)
        out[w] = res[w];
}

// ------- Pass 2: column-pair FFTs + ring binning. Block = (pair p, batch b). -------
__global__ void __launch_bounds__(128) pass2_cols() {
    __shared__ float2 A0[512];
    __shared__ float2 A1[512];
    __shared__ float2 B0[512];
    __shared__ float2 B1[512];
    __shared__ float sbin[NBINS * 4];

    int p  = blockIdx.x;                    // primary column 0..256
    int b  = blockIdx.y;
    int w2 = (512 - p) & 511;               // mirror column
    bool self = (w2 == p);                  // p == 0 or p == 256
    int tid = threadIdx.x;

    for (int i = tid; i < NBINS * 4; i += 128) sbin[i] = 0.0f;

    const float2* base = g_fft + (size_t)b * HD * WD;
    for (int h = tid; h < 512; h += 128) {
        A0[h] = base[(size_t)h * WD + p];
        B0[h] = base[(size_t)h * WD + w2];
    }
    float2* FA = fft512(A0, A1, tid);
    float2* FB = self ? FA : fft512(B0, B1, tid);   // condition uniform over block

    int fw = (p <= 255) ? p : p - 512;      // signed frequency of column
    float fw2 = (float)(fw * fw);
    const float scale = 1.0f / (512.0f * 512.0f);   // norm='forward'
    float mulf = self ? 1.0f : 2.0f;

    for (int kh = tid; kh < 512; kh += 128) {
        float2 P  = FA[kh];                             // Fz(kh, p)
        int   khm = (512 - kh) & 511;
        float2 Mc = FB[khm];                            // Fz(-kh, -p)
        float px = P.x * scale,  py = P.y * scale;
        float mx = Mc.x * scale, my = -Mc.y * scale;    // M = conj(Fz(-k))
        // F1 = (P+M)/2 ; F2 = -i*(P-M)/2
        float f1x = 0.5f * (px + mx), f1y = 0.5f * (py + my);
        float dx  = 0.5f * (px - mx), dy  = 0.5f * (py - my);
        float f2x = dy, f2y = -dx;
        float av  = f1x * f2x + f1y * f2y;              // Re(F1 conj F2)
        float bv  = f1y * f2x - f1x * f2y;              // Im(F1 conj F2)
        float c1  = f1x * f1x + f1y * f1y;
        float c2  = f2x * f2x + f2y * f2y;

        int fh = (kh <= 255) ? kh : kh - 512;
        float rr = sqrtf((float)(fh * fh) + fw2);
        int r = (int)rintf(rr);                         // round-half-even == jnp.round
        if (r > 256) r = 257;                           // drop bin

        atomicAdd(&sbin[r * 4 + 0], mulf * av);
        if (self) atomicAdd(&sbin[r * 4 + 1], bv);      // pair blocks: +b and -b cancel
        atomicAdd(&sbin[r * 4 + 2], mulf * c1);
        atomicAdd(&sbin[r * 4 + 3], mulf * c2);
    }
    __syncthreads();

    for (int i = tid; i < NBINS * 4; i += 128) {
        float v = sbin[i];
        if (v != 0.0f) {
            int r = i >> 2, c = i & 3;
            atomicAdd(&g_bins[(r * BD + b) * 4 + c], v);
        }
    }
}

// ---------------- Init / final ----------------
__global__ void zero_bins() {
    int i = blockIdx.x * blockDim.x + threadIdx.x;
    if (i < NBINS * BD * 4) g_bins[i] = 0.0f;
}

__global__ void __launch_bounds__(256) final_reduce(float* __restrict__ out) {
    __shared__ float red[256];
    int tid = threadIdx.x;
    float acc = 0.0f;
    for (int i = tid; i < NRING * BD; i += 256) {
        int r = i / BD, b = i % BD;
        const float* s = &g_bins[(r * BD + b) * 4];
        float Cr = s[0], Ci = s[1], C1 = s[2], C2 = s[3];
        float frc = sqrtf(Cr * Cr + Ci * Ci) / (sqrtf(C1 * C2) + 1e-8f);
        float d = 1.0f - frc;
        acc += d * d;
    }
    red[tid] = acc;
    __syncthreads();
    for (int s = 128; s > 0; s >>= 1) {
        if (tid < s) red[tid] += red[tid + s];
        __syncthreads();
    }
    if (tid == 0) out[0] = red[0] / (float)(NRING * BD);
}

extern "C" void kernel_launch(void* const* d_in, const int* in_sizes, int n_in,
                              void* d_out, int out_size) {
    const float* o = (const float*)d_in[0];   // output  (32,1,512,512) f32
    const float* t = (const float*)d_in[1];   // target  (32,1,512,512) f32
    float* out = (float*)d_out;

    zero_bins<<<(NBINS * BD * 4 + 255) / 256, 256>>>();
    pass1_rows<<<BD * HD, 128>>>(o, t);
    dim3 g2(NRING, BD);
    pass2_cols<<<g2, 128>>>();
    final_reduce<<<1, 256>>>(out);
}